// round 6
// baseline (speedup 1.0000x reference)
#include <cuda_runtime.h>
#include <cuda_bf16.h>
#include <cstdint>

// LinearEmbedded via mma.sync bf16 3-way split.
// out[a,b,d] = sum_c x[a,b,c]*W[r_b,c,d] + bias[r_b,d]; A=B=128, C=D=512.
// R5: tile 128(a) x 64(d), K-chunk 32, 2 stages (48KB), 256 thr, 2 CTAs/SM,
// single barrier per chunk. Grid (8,128) = 1024 CTAs.
// SMEM tiles in ldmatrix lane order: 16x16 bf16 tile = 32 contiguous 16B
// chunks, chunk index == lane index -> conflict-free LDSM.

__device__ int g_ridx[128];

__global__ void decode_idx_kernel(const unsigned int* __restrict__ p, int n) {
    __shared__ int not_i64;
    if (threadIdx.x == 0) not_i64 = 0;
    __syncthreads();
    if (threadIdx.x < 64) {
        if (p[2 * threadIdx.x + 1] != 0u) not_i64 = 1;
    }
    __syncthreads();
    int b = (int)threadIdx.x;
    if (b < n) g_ridx[b] = not_i64 ? (int)p[b] : (int)p[2 * b];
}

__device__ __forceinline__ uint32_t smem_u32(const void* p) {
    uint32_t a;
    asm("{ .reg .u64 t; cvta.to.shared.u64 t, %1; cvt.u32.u64 %0, t; }" : "=r"(a) : "l"(p));
    return a;
}

__device__ __forceinline__ void split2(float v0, float v1, uint32_t& hi, uint32_t& lo) {
    __nv_bfloat16 h0 = __float2bfloat16_rn(v0);
    __nv_bfloat16 h1 = __float2bfloat16_rn(v1);
    __nv_bfloat16 l0 = __float2bfloat16_rn(v0 - __bfloat162float(h0));
    __nv_bfloat16 l1 = __float2bfloat16_rn(v1 - __bfloat162float(h1));
    __nv_bfloat162 hp; hp.x = h0; hp.y = h1;
    __nv_bfloat162 lp; lp.x = l0; lp.y = l1;
    hi = *(uint32_t*)&hp;
    lo = *(uint32_t*)&lp;
}

__device__ __forceinline__ void ldsm4(uint32_t* r, uint32_t addr) {
    asm volatile("ldmatrix.sync.aligned.m8n8.x4.shared.b16 {%0,%1,%2,%3}, [%4];"
        : "=r"(r[0]), "=r"(r[1]), "=r"(r[2]), "=r"(r[3]) : "r"(addr));
}

__device__ __forceinline__ void mma16816(float* d, const uint32_t* a, uint32_t b0, uint32_t b1) {
    asm volatile("mma.sync.aligned.m16n8k16.row.col.f32.bf16.bf16.f32 "
        "{%0,%1,%2,%3}, {%4,%5,%6,%7}, {%8,%9}, {%0,%1,%2,%3};"
        : "+f"(d[0]), "+f"(d[1]), "+f"(d[2]), "+f"(d[3])
        : "r"(a[0]), "r"(a[1]), "r"(a[2]), "r"(a[3]), "r"(b0), "r"(b1));
}

// Per-stage layout (24 KB):
//   AHI 0      (x hi:  2 k16 x 8 tiles x 512B = 8 KB)
//   ALO 8192   (x lo:  8 KB)
//   BHI 16384  (W hi:  2 k16 x 4 tiles x 512B = 4 KB)
//   BLO 20480  (W lo:  4 KB)
#define STAGE_BYTES 24576
#define AHI_OFF 0
#define ALO_OFF 8192
#define BHI_OFF 16384
#define BLO_OFF 20480
#define SMEM_TOTAL (2 * STAGE_BYTES)

__global__ __launch_bounds__(256, 2)
void linemb_mma(const float* __restrict__ x,
                const float* __restrict__ w,
                const float* __restrict__ bias,
                float* __restrict__ out) {
    extern __shared__ char smem[];
    const uint32_t sb = smem_u32(smem);

    const int tid  = (int)threadIdx.x;
    const int wid  = tid >> 5;
    const int lane = tid & 31;
    const int b    = (int)blockIdx.y;
    const int d0   = (int)blockIdx.x * 64;
    const int r    = g_ridx[b];

    const float* __restrict__ xb = x + (size_t)b * 512;          // + a*65536 + c
    const float* __restrict__ wr = w + (size_t)r * 512 * 512;    // + c*512 + d
    const float* __restrict__ br = bias + (size_t)r * 512;

    // W loader: 64 d x 32 k per chunk; thread -> (d, k-octet), 8 elems.
    const int w_d   = tid & 63;
    const int w_oct = tid >> 6;           // 0..3
    // x loader: 128 a x 32 k per chunk; thread -> (a, 2 k-octets), 16 elems.
    const int a_idx = tid & 127;
    const int x_o0  = (tid >> 7) * 2;     // 0 or 2

    uint32_t boff, aoff[2];
    {
        const int n = w_d & 15, t16 = w_d >> 4;
        const int k16 = w_oct >> 1, oc = w_oct & 1;
        boff = (uint32_t)((k16 * 4 + t16) * 512 + ((n & 7) + 8 * (oc + 2 * (n >> 3))) * 16);
    }
    {
        const int n = a_idx & 15, t16 = a_idx >> 4;
        #pragma unroll
        for (int j = 0; j < 2; ++j) {
            const int o = x_o0 + j, k16 = o >> 1, oc = o & 1;
            aoff[j] = (uint32_t)((k16 * 8 + t16) * 512 + (n + 16 * oc) * 16);
        }
    }

    float wv[8], xv[16];

    // ---- prefetch chunk 0 ----
    {
        #pragma unroll
        for (int i = 0; i < 8; ++i)
            wv[i] = __ldg(wr + (size_t)(w_oct * 8 + i) * 512 + d0 + w_d);
        #pragma unroll
        for (int j = 0; j < 2; ++j) {
            const int o = x_o0 + j;
            const float4 p0 = *(const float4*)(xb + (size_t)a_idx * 65536 + o * 8);
            const float4 p1 = *(const float4*)(xb + (size_t)a_idx * 65536 + o * 8 + 4);
            xv[j * 8 + 0] = p0.x; xv[j * 8 + 1] = p0.y; xv[j * 8 + 2] = p0.z; xv[j * 8 + 3] = p0.w;
            xv[j * 8 + 4] = p1.x; xv[j * 8 + 5] = p1.y; xv[j * 8 + 6] = p1.z; xv[j * 8 + 7] = p1.w;
        }
    }

    float acc[2][4][4];
    #pragma unroll
    for (int mt = 0; mt < 2; ++mt)
        #pragma unroll
        for (int nb = 0; nb < 4; ++nb)
            #pragma unroll
            for (int q = 0; q < 4; ++q)
                acc[mt][nb][q] = 0.0f;

    const int wm = wid & 3;   // 4 m-groups of 32 (a)
    const int wn = wid >> 2;  // 2 n-groups of 32 (d)

    for (int ch = 0; ch < 16; ++ch) {        // 16 chunks of K=32
        const uint32_t st = sb + (uint32_t)((ch & 1) * STAGE_BYTES);

        // ---- convert + store this chunk into stage ----
        {
            uint32_t h[4], l[4];
            #pragma unroll
            for (int p = 0; p < 4; ++p)
                split2(wv[2 * p], wv[2 * p + 1], h[p], l[p]);
            asm volatile("st.shared.v4.b32 [%0], {%1,%2,%3,%4};" :: "r"(st + BHI_OFF + boff), "r"(h[0]), "r"(h[1]), "r"(h[2]), "r"(h[3]) : "memory");
            asm volatile("st.shared.v4.b32 [%0], {%1,%2,%3,%4};" :: "r"(st + BLO_OFF + boff), "r"(l[0]), "r"(l[1]), "r"(l[2]), "r"(l[3]) : "memory");
            #pragma unroll
            for (int j = 0; j < 2; ++j) {
                #pragma unroll
                for (int p = 0; p < 4; ++p)
                    split2(xv[j * 8 + 2 * p], xv[j * 8 + 2 * p + 1], h[p], l[p]);
                asm volatile("st.shared.v4.b32 [%0], {%1,%2,%3,%4};" :: "r"(st + AHI_OFF + aoff[j]), "r"(h[0]), "r"(h[1]), "r"(h[2]), "r"(h[3]) : "memory");
                asm volatile("st.shared.v4.b32 [%0], {%1,%2,%3,%4};" :: "r"(st + ALO_OFF + aoff[j]), "r"(l[0]), "r"(l[1]), "r"(l[2]), "r"(l[3]) : "memory");
            }
        }

        // ---- prefetch next chunk into registers ----
        if (ch + 1 < 16) {
            const int k0 = (ch + 1) * 32;
            #pragma unroll
            for (int i = 0; i < 8; ++i)
                wv[i] = __ldg(wr + (size_t)(k0 + w_oct * 8 + i) * 512 + d0 + w_d);
            #pragma unroll
            for (int j = 0; j < 2; ++j) {
                const int o = x_o0 + j;
                const float4 p0 = *(const float4*)(xb + (size_t)a_idx * 65536 + k0 + o * 8);
                const float4 p1 = *(const float4*)(xb + (size_t)a_idx * 65536 + k0 + o * 8 + 4);
                xv[j * 8 + 0] = p0.x; xv[j * 8 + 1] = p0.y; xv[j * 8 + 2] = p0.z; xv[j * 8 + 3] = p0.w;
                xv[j * 8 + 4] = p1.x; xv[j * 8 + 5] = p1.y; xv[j * 8 + 6] = p1.z; xv[j * 8 + 7] = p1.w;
            }
        }

        // Single barrier per chunk: with 2 stages, this also orders
        // compute(ch-2) (same stage) before the stores above on all warps.
        __syncthreads();

        // ---- compute: 2 k16-steps ----
        #pragma unroll
        for (int k16 = 0; k16 < 2; ++k16) {
            uint32_t ah[2][4], al[2][4], bh[2][4], bl[2][4];
            const uint32_t lof = (uint32_t)lane * 16;
            #pragma unroll
            for (int mt = 0; mt < 2; ++mt) {
                const uint32_t toff = (uint32_t)((k16 * 8 + wm * 2 + mt) * 512) + lof;
                ldsm4(ah[mt], st + AHI_OFF + toff);
                ldsm4(al[mt], st + ALO_OFF + toff);
            }
            #pragma unroll
            for (int nt = 0; nt < 2; ++nt) {
                const uint32_t toff = (uint32_t)((k16 * 4 + wn * 2 + nt) * 512) + lof;
                ldsm4(bh[nt], st + BHI_OFF + toff);
                ldsm4(bl[nt], st + BLO_OFF + toff);
            }
            #pragma unroll
            for (int mt = 0; mt < 2; ++mt) {
                #pragma unroll
                for (int nb = 0; nb < 4; ++nb) {
                    const int nt = nb >> 1, hh = (nb & 1) * 2;
                    mma16816(acc[mt][nb], ah[mt], bh[nt][hh], bh[nt][hh + 1]);
                    mma16816(acc[mt][nb], ah[mt], bl[nt][hh], bl[nt][hh + 1]);
                    mma16816(acc[mt][nb], al[mt], bh[nt][hh], bh[nt][hh + 1]);
                }
            }
        }
    }

    // ---- epilogue: add bias, store out[a][b][d] ----
    const int tq = lane & 3;    // -> d pair
    const int tg = lane >> 2;   // -> row within 8
    #pragma unroll
    for (int nb = 0; nb < 4; ++nb) {
        const int d = d0 + wn * 32 + nb * 8 + 2 * tq;
        const float2 bv = *(const float2*)(br + d);
        #pragma unroll
        for (int mt = 0; mt < 2; ++mt) {
            const int a0r = wm * 32 + mt * 16 + tg;
            float2 o0, o1;
            o0.x = acc[mt][nb][0] + bv.x;
            o0.y = acc[mt][nb][1] + bv.y;
            o1.x = acc[mt][nb][2] + bv.x;
            o1.y = acc[mt][nb][3] + bv.y;
            *(float2*)(out + ((size_t)a0r * 128 + b) * 512 + d)       = o0;
            *(float2*)(out + ((size_t)(a0r + 8) * 128 + b) * 512 + d) = o1;
        }
    }
}

extern "C" void kernel_launch(void* const* d_in, const int* in_sizes, int n_in,
                              void* d_out, int out_size) {
    const float*        x    = (const float*)d_in[0];
    const unsigned int* ridx = (const unsigned int*)d_in[1];
    const float*        w    = (const float*)d_in[2];
    const float*        bias = (const float*)d_in[3];
    float*              out  = (float*)d_out;

    const int Bn = in_sizes[1] > 128 ? 128 : in_sizes[1];
    decode_idx_kernel<<<1, 128>>>(ridx, Bn);

    static int smem_set = 0;
    if (!smem_set) {
        cudaFuncSetAttribute(linemb_mma, cudaFuncAttributeMaxDynamicSharedMemorySize, SMEM_TOTAL);
        smem_set = 1;
    }
    dim3 grid(8, 128);   // (d-tiles, b)
    linemb_mma<<<grid, 256, SMEM_TOTAL>>>(x, w, bias, out);
}

// round 8
// speedup vs baseline: 2.4675x; 2.4675x over previous
#include <cuda_runtime.h>
#include <cuda_fp16.h>
#include <cstdint>

// LinearEmbedded via single-pass fp16 mma.sync (fp32 accumulate).
// out[a,b,d] = sum_c x[a,b,c]*W[r_b,c,d] + bias[r_b,d]; A=B=128, C=D=512.
// R7 (= R6 resubmit after infra failure): CTA tile 128(a) x 128(d), K-chunk 32,
// 2 stages x 16KB static smem, 256 thr, 2 CTAs/SM, 8 warps as 2(m)x4(n)
// -> warp tile 64x32.
// fp16 quantization error ~2^-12 (norm rel_err ~2e-4 < 1e-3 threshold).
// SMEM tiles in ldmatrix lane order: each 16x16 half tile = 32 contiguous
// 16B chunks, chunk index == lane index -> conflict-free LDSM.

__device__ int g_ridx[128];

__global__ void decode_idx_kernel(const unsigned int* __restrict__ p, int n) {
    __shared__ int not_i64;
    if (threadIdx.x == 0) not_i64 = 0;
    __syncthreads();
    if (threadIdx.x < 64) {
        if (p[2 * threadIdx.x + 1] != 0u) not_i64 = 1;
    }
    __syncthreads();
    int b = (int)threadIdx.x;
    if (b < n) g_ridx[b] = not_i64 ? (int)p[b] : (int)p[2 * b];
}

__device__ __forceinline__ uint32_t smem_u32(const void* p) {
    uint32_t a;
    asm("{ .reg .u64 t; cvta.to.shared.u64 t, %1; cvt.u32.u64 %0, t; }" : "=r"(a) : "l"(p));
    return a;
}

__device__ __forceinline__ uint32_t cvt2(float v0, float v1) {
    __half2 h = __floats2half2_rn(v0, v1);
    return *(uint32_t*)&h;
}

__device__ __forceinline__ void ldsm4(uint32_t* r, uint32_t addr) {
    asm volatile("ldmatrix.sync.aligned.m8n8.x4.shared.b16 {%0,%1,%2,%3}, [%4];"
        : "=r"(r[0]), "=r"(r[1]), "=r"(r[2]), "=r"(r[3]) : "r"(addr));
}

__device__ __forceinline__ void mma16816(float* d, const uint32_t* a, uint32_t b0, uint32_t b1) {
    asm volatile("mma.sync.aligned.m16n8k16.row.col.f32.f16.f16.f32 "
        "{%0,%1,%2,%3}, {%4,%5,%6,%7}, {%8,%9}, {%0,%1,%2,%3};"
        : "+f"(d[0]), "+f"(d[1]), "+f"(d[2]), "+f"(d[3])
        : "r"(a[0]), "r"(a[1]), "r"(a[2]), "r"(a[3]), "r"(b0), "r"(b1));
}

// Per-stage (16 KB): A(x) [k16:2][tile16:8]*512B = 8KB at 0,
//                    B(W) [k16:2][tile16:8]*512B = 8KB at 8192.
#define A_OFF 0
#define B_OFF 8192
#define STAGE_BYTES 16384

__global__ __launch_bounds__(256, 2)
void linemb_mma(const float* __restrict__ x,
                const float* __restrict__ w,
                const float* __restrict__ bias,
                float* __restrict__ out) {
    __shared__ __align__(16) char smem[2 * STAGE_BYTES];
    const uint32_t sb = smem_u32(smem);

    const int tid  = (int)threadIdx.x;
    const int wid  = tid >> 5;
    const int lane = tid & 31;
    const int b    = (int)blockIdx.y;
    const int d0   = (int)blockIdx.x * 128;
    const int r    = g_ridx[b];

    const float* __restrict__ xb = x + (size_t)b * 512;          // + a*65536 + c
    const float* __restrict__ wr = w + (size_t)r * 512 * 512;    // + c*512 + d
    const float* __restrict__ br = bias + (size_t)r * 512;

    // Loaders: each thread handles 2 k-octets (16 values) of one row.
    const int row  = tid & 127;          // W: d row; x: a row
    const int oct0 = (tid >> 7) * 2;     // first octet (0 or 2)

    // SMEM chunk offsets within stage for the 2 octets.
    uint32_t aoff[2], boff[2];
    {
        const int n = row & 15, t16 = row >> 4;
        #pragma unroll
        for (int j = 0; j < 2; ++j) {
            const int o = oct0 + j, k16 = o >> 1, oc = o & 1;
            // A (x, m-operand): chunk = (n&7) + 8*((n>>3)&1) + 16*oct
            aoff[j] = (uint32_t)((k16 * 8 + t16) * 512 + ((n & 7) + 8 * ((n >> 3) & 1) + 16 * oc) * 16);
            // B (W, n-operand): chunk = (n&7) + 8*(oct + 2*(n>>3))
            boff[j] = (uint32_t)((k16 * 8 + t16) * 512 + ((n & 7) + 8 * (oc + 2 * (n >> 3))) * 16);
        }
    }

    uint32_t wh[8], xh[8];   // prefetched half2 data (2 octets x 4)

    // ---- prefetch + convert chunk 0 ----
    #pragma unroll
    for (int j = 0; j < 2; ++j) {
        const int o = oct0 + j;
        float v[8];
        #pragma unroll
        for (int i = 0; i < 8; ++i)
            v[i] = __ldg(wr + (size_t)(o * 8 + i) * 512 + d0 + row);
        #pragma unroll
        for (int p = 0; p < 4; ++p)
            wh[j * 4 + p] = cvt2(v[2 * p], v[2 * p + 1]);
        const float4 p0 = *(const float4*)(xb + (size_t)row * 65536 + o * 8);
        const float4 p1 = *(const float4*)(xb + (size_t)row * 65536 + o * 8 + 4);
        xh[j * 4 + 0] = cvt2(p0.x, p0.y);
        xh[j * 4 + 1] = cvt2(p0.z, p0.w);
        xh[j * 4 + 2] = cvt2(p1.x, p1.y);
        xh[j * 4 + 3] = cvt2(p1.z, p1.w);
    }

    float acc[4][4][4];
    #pragma unroll
    for (int mt = 0; mt < 4; ++mt)
        #pragma unroll
        for (int nb = 0; nb < 4; ++nb)
            #pragma unroll
            for (int q = 0; q < 4; ++q)
                acc[mt][nb][q] = 0.0f;

    const int wm = wid & 1;   // 2 m-groups of 64 (a)
    const int wn = wid >> 1;  // 4 n-groups of 32 (d)

    for (int ch = 0; ch < 16; ++ch) {        // 16 chunks of K=32
        const uint32_t st = sb + (uint32_t)((ch & 1) * STAGE_BYTES);

        // ---- store prefetched chunk into stage ----
        #pragma unroll
        for (int j = 0; j < 2; ++j) {
            asm volatile("st.shared.v4.b32 [%0], {%1,%2,%3,%4};"
                :: "r"(st + A_OFF + aoff[j]), "r"(xh[j*4+0]), "r"(xh[j*4+1]), "r"(xh[j*4+2]), "r"(xh[j*4+3]) : "memory");
            asm volatile("st.shared.v4.b32 [%0], {%1,%2,%3,%4};"
                :: "r"(st + B_OFF + boff[j]), "r"(wh[j*4+0]), "r"(wh[j*4+1]), "r"(wh[j*4+2]), "r"(wh[j*4+3]) : "memory");
        }

        // ---- prefetch + convert next chunk ----
        if (ch + 1 < 16) {
            const int k0 = (ch + 1) * 32;
            #pragma unroll
            for (int j = 0; j < 2; ++j) {
                const int o = oct0 + j;
                float v[8];
                #pragma unroll
                for (int i = 0; i < 8; ++i)
                    v[i] = __ldg(wr + (size_t)(k0 + o * 8 + i) * 512 + d0 + row);
                #pragma unroll
                for (int p = 0; p < 4; ++p)
                    wh[j * 4 + p] = cvt2(v[2 * p], v[2 * p + 1]);
                const float4 p0 = *(const float4*)(xb + (size_t)row * 65536 + k0 + o * 8);
                const float4 p1 = *(const float4*)(xb + (size_t)row * 65536 + k0 + o * 8 + 4);
                xh[j * 4 + 0] = cvt2(p0.x, p0.y);
                xh[j * 4 + 1] = cvt2(p0.z, p0.w);
                xh[j * 4 + 2] = cvt2(p1.x, p1.y);
                xh[j * 4 + 3] = cvt2(p1.z, p1.w);
            }
        }

        // Single barrier: also orders other warps' compute(ch-2) on this
        // stage before our stores of chunk ch (via barrier of ch-1).
        __syncthreads();

        // ---- compute: 2 k16-steps ----
        #pragma unroll
        for (int k16 = 0; k16 < 2; ++k16) {
            uint32_t ah[4][4], bh[2][4];
            const uint32_t lof = (uint32_t)lane * 16;
            #pragma unroll
            for (int mt = 0; mt < 4; ++mt)
                ldsm4(ah[mt], st + A_OFF + (uint32_t)((k16 * 8 + wm * 4 + mt) * 512) + lof);
            #pragma unroll
            for (int nt = 0; nt < 2; ++nt)
                ldsm4(bh[nt], st + B_OFF + (uint32_t)((k16 * 8 + wn * 2 + nt) * 512) + lof);
            #pragma unroll
            for (int mt = 0; mt < 4; ++mt) {
                #pragma unroll
                for (int nb = 0; nb < 4; ++nb) {
                    const int nt = nb >> 1, hh = (nb & 1) * 2;
                    mma16816(acc[mt][nb], ah[mt], bh[nt][hh], bh[nt][hh + 1]);
                }
            }
        }
    }

    // ---- epilogue: add bias, store out[a][b][d] ----
    const int tq = lane & 3;    // -> d pair
    const int tg = lane >> 2;   // -> row within 8
    #pragma unroll
    for (int nb = 0; nb < 4; ++nb) {
        const int d = d0 + wn * 32 + nb * 8 + 2 * tq;
        const float2 bv = *(const float2*)(br + d);
        #pragma unroll
        for (int mt = 0; mt < 4; ++mt) {
            const int a0r = (wm * 4 + mt) * 16 + tg;
            float2 o0, o1;
            o0.x = acc[mt][nb][0] + bv.x;
            o0.y = acc[mt][nb][1] + bv.y;
            o1.x = acc[mt][nb][2] + bv.x;
            o1.y = acc[mt][nb][3] + bv.y;
            *(float2*)(out + ((size_t)a0r * 128 + b) * 512 + d)       = o0;
            *(float2*)(out + ((size_t)(a0r + 8) * 128 + b) * 512 + d) = o1;
        }
    }
}

extern "C" void kernel_launch(void* const* d_in, const int* in_sizes, int n_in,
                              void* d_out, int out_size) {
    const float*        x    = (const float*)d_in[0];
    const unsigned int* ridx = (const unsigned int*)d_in[1];
    const float*        w    = (const float*)d_in[2];
    const float*        bias = (const float*)d_in[3];
    float*              out  = (float*)d_out;

    const int Bn = in_sizes[1] > 128 ? 128 : in_sizes[1];
    decode_idx_kernel<<<1, 128>>>(ridx, Bn);

    dim3 grid(4, 128);   // (d-tiles, b)
    linemb_mma<<<grid, 256>>>(x, w, bias, out);
}